// round 9
// baseline (speedup 1.0000x reference)
#include <cuda_runtime.h>
#include <cstdint>

// Problem shape (fixed for this instance)
#define NUM_SP 2048
#define CCH    64
#define NPIX   (1024 * 1024)

#define TILE_PX 64
#define ROW_WORDS 68          // 64 floats + 16B pad -> 272 B row stride (16B aligned)

// Gather tiling
#define QITER  16
#define PIX_PER_BLOCK_G (QITER * 256 * 4)  // 16384 pixels

// Scratch. 256B-aligned so each segment row (256 B) is a clean bulk target.
__device__ __align__(256) float g_sums[NUM_SP * CCH];
__device__ float g_cnt[NUM_SP];

// -------------------------------------------------------------------------
// Kernel 1: zero scratch (vectorized)
// -------------------------------------------------------------------------
__global__ void zero_kernel() {
    int i = blockIdx.x * blockDim.x + threadIdx.x;
    reinterpret_cast<float4*>(g_sums)[i] = make_float4(0.f, 0.f, 0.f, 0.f);
    if (i < NUM_SP / 4)
        reinterpret_cast<float4*>(g_cnt)[i] = make_float4(0.f, 0.f, 0.f, 0.f);
}

// Profiling alignment shims: ncu captures overall launch #4 -> accum.
__global__ void noop_kernel() {}
__global__ void noop_kernel2() {}

__device__ __forceinline__ uint32_t smem_u32(const void* p) {
    uint32_t a;
    asm("{ .reg .u64 t; cvta.to.shared.u64 t, %1; cvt.u32.u64 %0, t; }"
        : "=r"(a) : "l"(p));
    return a;
}

// Row permutation: px = 4f+k  ->  rowIdx = (f&7) | (k<<3) | ((f>>3)<<5)
// Bijective on 0..63; makes the phase-1 STS pattern hit 8 distinct banks
// per half-warp (2-way conflict) while keeping each pixel row contiguous.
__device__ __forceinline__ int row_of(int f, int k) {
    return (f & 7) | (k << 3) | ((f >> 3) << 5);
}

// -------------------------------------------------------------------------
// Kernel 2: accumulate sums + counts via BULK ASYNC REDUCE.
// Phase 1: coalesced streaming LDG.128 on x, scalar-STS into row-permuted
//   linear smem s_row[rowIdx][64ch] (272 B stride).
// Phase 2: one cp.reduce.async.bulk (256 B, f32 add) per pixel, issued
//   SMEM -> L2 directly — no L1tex wavefronts, no per-lane RED path.
// -------------------------------------------------------------------------
__global__ void __launch_bounds__(256) accum_kernel(
    const float* __restrict__ x, const int* __restrict__ sp) {
    __shared__ __align__(16) float s_row[TILE_PX * ROW_WORDS];  // 17.4 KB
    __shared__ int s_seg[TILE_PX];

    int t  = threadIdx.x;
    int p0 = blockIdx.x * TILE_PX;

    if (t < TILE_PX / 4) {
        int4 v = reinterpret_cast<const int4*>(sp + p0)[t];
        s_seg[t * 4 + 0] = v.x;
        s_seg[t * 4 + 1] = v.y;
        s_seg[t * 4 + 2] = v.z;
        s_seg[t * 4 + 3] = v.w;
    }

    // Phase 1: load x tile coalesced, scatter into permuted pixel rows
#pragma unroll
    for (int i = 0; i < 4; i++) {
        int idx = i * 256 + t;          // 0..1023
        int c   = idx >> 4;             // channel 0..63
        int f   = idx & 15;             // float4 column (4 pixels)
        float4 v = __ldcs(reinterpret_cast<const float4*>(
            x + (size_t)c * NPIX + p0 + f * 4));
#pragma unroll
        for (int k = 0; k < 4; k++)
            s_row[row_of(f, k) * ROW_WORDS + c] = (&v.x)[k];
    }
    __syncthreads();

    // Counts: one scalar RED per pixel
    if (t < TILE_PX) atomicAdd(&g_cnt[s_seg[t]], 1.0f);

    // Phase 2: one bulk reduce per pixel (threads 64..255 idle here)
    if (t < TILE_PX) {
        int f = t >> 2, k = t & 3;
        uint32_t saddr = smem_u32(&s_row[row_of(f, k) * ROW_WORDS]);
        float*   gaddr = &g_sums[(size_t)s_seg[t] * CCH];
        asm volatile("fence.proxy.async.shared::cta;" ::: "memory");
        asm volatile(
            "cp.reduce.async.bulk.global.shared::cta.bulk_group.add.f32 "
            "[%0], [%1], %2;"
            :: "l"(gaddr), "r"(saddr), "r"(CCH * 4) : "memory");
        asm volatile("cp.async.bulk.commit_group;" ::: "memory");
    }
    // No wait: smem not reused; kernel completion drains the bulk group.
}

// -------------------------------------------------------------------------
// Kernel 3: gather/broadcast, smem-staged means (protected win),
// streaming stores on out.
// -------------------------------------------------------------------------
__global__ void __launch_bounds__(256) gather_kernel(
    const int* __restrict__ sp, float* __restrict__ out) {
    __shared__ float4 s_means[NUM_SP];   // 32 KB

    int tid = threadIdx.x;
    int cg  = blockIdx.y;
    int blockPixBase = blockIdx.x * PIX_PER_BLOCK_G;

#pragma unroll
    for (int i = 0; i < NUM_SP / 256; i++) {
        int s = i * 256 + tid;
        float4 sum = *reinterpret_cast<const float4*>(
            &g_sums[(size_t)s * CCH + cg * 4]);
        float inv = __frcp_rn(fmaxf(g_cnt[s], 1.0f));
        s_means[s] = make_float4(sum.x * inv, sum.y * inv, sum.z * inv, sum.w * inv);
    }
    __syncthreads();

#pragma unroll
    for (int q = 0; q < QITER; q++) {
        int p = blockPixBase + (q * 256 + tid) * 4;
        int4 s4 = *reinterpret_cast<const int4*>(sp + p);

        float4 a = s_means[s4.x];
        float4 b = s_means[s4.y];
        float4 c = s_means[s4.z];
        float4 d = s_means[s4.w];

        __stcs(reinterpret_cast<float4*>(out + (size_t)(cg * 4 + 0) * NPIX + p),
               make_float4(a.x, b.x, c.x, d.x));
        __stcs(reinterpret_cast<float4*>(out + (size_t)(cg * 4 + 1) * NPIX + p),
               make_float4(a.y, b.y, c.y, d.y));
        __stcs(reinterpret_cast<float4*>(out + (size_t)(cg * 4 + 2) * NPIX + p),
               make_float4(a.z, b.z, c.z, d.z));
        __stcs(reinterpret_cast<float4*>(out + (size_t)(cg * 4 + 3) * NPIX + p),
               make_float4(a.w, b.w, c.w, d.w));
    }
}

// -------------------------------------------------------------------------
// kernel_launch: graph-capturable (kernel launches only)
// Launch order keeps accum at overall position #4 (ncu capture slot).
// -------------------------------------------------------------------------
extern "C" void kernel_launch(void* const* d_in, const int* in_sizes, int n_in,
                              void* d_out, int out_size) {
    const float* x  = (const float*)d_in[0];
    const int*   sp = (const int*)d_in[1];
    float*       out = (float*)d_out;

    const int threads = 256;
    const int zero_blocks  = (NUM_SP * CCH / 4) / threads;   // 128
    const int accum_blocks = NPIX / TILE_PX;                 // 16384

    zero_kernel<<<zero_blocks, threads>>>();
    noop_kernel<<<1, 1>>>();
    noop_kernel2<<<1, 1>>>();
    accum_kernel<<<accum_blocks, threads>>>(x, sp);
    gather_kernel<<<dim3(NPIX / PIX_PER_BLOCK_G, CCH / 4), threads>>>(sp, out);
}

// round 10
// speedup vs baseline: 1.0118x; 1.0118x over previous
#include <cuda_runtime.h>
#include <cstdint>

// Problem shape (fixed for this instance)
#define NUM_SP 2048
#define CCH    64
#define NPIX   (1024 * 1024)

#define TILE_PX 64
#define PX_PER_BLOCK (2 * TILE_PX)         // double-buffered accum: 128 px

// Gather tiling
#define QITER  16
#define PIX_PER_BLOCK_G (QITER * 256 * 4)  // 16384 pixels

// Scratch (allocation-free rule: __device__ globals)
__device__ float g_sums[NUM_SP * CCH];   // [S, C] row-major, 512 KB (L2-hot)
__device__ float g_cnt[NUM_SP];

// PDL wait: block until the immediately-preceding grid's memory is visible.
__device__ __forceinline__ void grid_dep_wait() {
    asm volatile("griddepcontrol.wait;" ::: "memory");
}

// -------------------------------------------------------------------------
// Kernel 1: zero scratch (vectorized)
// -------------------------------------------------------------------------
__global__ void zero_kernel() {
    int i = blockIdx.x * blockDim.x + threadIdx.x;
    reinterpret_cast<float4*>(g_sums)[i] = make_float4(0.f, 0.f, 0.f, 0.f);
    if (i < NUM_SP / 4)
        reinterpret_cast<float4*>(g_cnt)[i] = make_float4(0.f, 0.f, 0.f, 0.f);
}

// Profiling alignment shims (before zero so slot #4 = accum, and so the
// zero->accum PDL adjacency is preserved).
__global__ void noop_kernel() {}
__global__ void noop_kernel2() {}

// -------------------------------------------------------------------------
// Vectorized fire-and-forget global reduction (no "memory" clobber).
// -------------------------------------------------------------------------
__device__ __forceinline__ void red_add_v4(float* addr, float a, float b,
                                           float c, float d) {
    asm volatile("red.global.add.v4.f32 [%0], {%1, %2, %3, %4};"
                 :: "l"(addr), "f"(a), "f"(b), "f"(c), "f"(d));
}

// -------------------------------------------------------------------------
// Kernel 2: accumulate sums + counts — double-buffered (protected R8 body)
// + PDL: launches concurrently with zero_kernel; all work up to the first
// RED (x LDG, smem transpose) runs under zero's tail, then grid_dep_wait()
// guarantees sums/cnt are zeroed before any atomic lands.
// -------------------------------------------------------------------------
__global__ void __launch_bounds__(256) accum_kernel(
    const float* __restrict__ x, const int* __restrict__ sp) {
    __shared__ float4 s_t[2][TILE_PX * 16];   // 2 x 16 KB, swizzled [px][c4]
    __shared__ int    s_seg[PX_PER_BLOCK];

    int t  = threadIdx.x;
    int p0 = blockIdx.x * PX_PER_BLOCK;

    if (t < PX_PER_BLOCK / 4) {
        int4 v = reinterpret_cast<const int4*>(sp + p0)[t];
        s_seg[t * 4 + 0] = v.x;
        s_seg[t * 4 + 1] = v.y;
        s_seg[t * 4 + 2] = v.z;
        s_seg[t * 4 + 3] = v.w;
    }

    float* s_f0 = reinterpret_cast<float*>(s_t[0]);
    float* s_f1 = reinterpret_cast<float*>(s_t[1]);

    // ---- Tile 0: load + transpose-store (no sums access: pre-wait) ----
#pragma unroll
    for (int i = 0; i < 4; i++) {
        int idx = i * 256 + t;
        int c   = idx >> 4;
        int f   = idx & 15;
        float4 v = __ldcs(reinterpret_cast<const float4*>(
            x + (size_t)c * NPIX + p0 + f * 4));
        int c4 = c >> 2, comp = c & 3;
#pragma unroll
        for (int k = 0; k < 4; k++) {
            int px   = f * 4 + k;
            int slot = px * 16 + (c4 ^ ((px >> 2) & 15));
            s_f0[slot * 4 + comp] = (&v.x)[k];
        }
    }
    __syncthreads();

    // ---- Tile 1: issue loads early (into registers) ----
    float4 pre[4];
#pragma unroll
    for (int i = 0; i < 4; i++) {
        int idx = i * 256 + t;
        int c   = idx >> 4;
        int f   = idx & 15;
        pre[i] = __ldcs(reinterpret_cast<const float4*>(
            x + (size_t)c * NPIX + p0 + TILE_PX + f * 4));
    }

    // PDL: zero_kernel's writes must be visible before any atomic below.
    grid_dep_wait();

    // Counts: one atomic per pixel (128 lanes)
    if (t < PX_PER_BLOCK) atomicAdd(&g_cnt[s_seg[t]], 1.0f);

    // ---- Tile 0: REDs (overlap tile-1 DRAM latency) ----
#pragma unroll
    for (int r = 0; r < 4; r++) {
        int pair = r * 256 + t;
        int px   = pair >> 4;
        int cg   = pair & 15;
        int seg  = s_seg[px];
        float4 v = s_t[0][px * 16 + (cg ^ ((px >> 2) & 15))];
        red_add_v4(&g_sums[(size_t)seg * CCH + cg * 4], v.x, v.y, v.z, v.w);
    }

    // ---- Tile 1: transpose-store from regs ----
#pragma unroll
    for (int i = 0; i < 4; i++) {
        int idx = i * 256 + t;
        int c   = idx >> 4;
        int f   = idx & 15;
        int c4 = c >> 2, comp = c & 3;
#pragma unroll
        for (int k = 0; k < 4; k++) {
            int px   = f * 4 + k;
            int slot = px * 16 + (c4 ^ ((px >> 2) & 15));
            s_f1[slot * 4 + comp] = (&pre[i].x)[k];
        }
    }
    __syncthreads();

    // ---- Tile 1: REDs ----
#pragma unroll
    for (int r = 0; r < 4; r++) {
        int pair = r * 256 + t;
        int px   = pair >> 4;
        int cg   = pair & 15;
        int seg  = s_seg[TILE_PX + px];
        float4 v = s_t[1][px * 16 + (cg ^ ((px >> 2) & 15))];
        red_add_v4(&g_sums[(size_t)seg * CCH + cg * 4], v.x, v.y, v.z, v.w);
    }
}

// -------------------------------------------------------------------------
// Kernel 3: gather/broadcast, smem-staged means (protected body) + PDL:
// launches while accum drains; waits before the staging reads of g_sums.
// -------------------------------------------------------------------------
__global__ void __launch_bounds__(256) gather_kernel(
    const int* __restrict__ sp, float* __restrict__ out) {
    __shared__ float4 s_means[NUM_SP];   // 32 KB

    int tid = threadIdx.x;
    int cg  = blockIdx.y;
    int blockPixBase = blockIdx.x * PIX_PER_BLOCK_G;

    // PDL: all accum REDs must be visible before staging.
    grid_dep_wait();

#pragma unroll
    for (int i = 0; i < NUM_SP / 256; i++) {
        int s = i * 256 + tid;
        float4 sum = *reinterpret_cast<const float4*>(
            &g_sums[(size_t)s * CCH + cg * 4]);
        float inv = __frcp_rn(fmaxf(g_cnt[s], 1.0f));
        s_means[s] = make_float4(sum.x * inv, sum.y * inv, sum.z * inv, sum.w * inv);
    }
    __syncthreads();

#pragma unroll
    for (int q = 0; q < QITER; q++) {
        int p = blockPixBase + (q * 256 + tid) * 4;
        int4 s4 = *reinterpret_cast<const int4*>(sp + p);

        float4 a = s_means[s4.x];
        float4 b = s_means[s4.y];
        float4 c = s_means[s4.z];
        float4 d = s_means[s4.w];

        __stcs(reinterpret_cast<float4*>(out + (size_t)(cg * 4 + 0) * NPIX + p),
               make_float4(a.x, b.x, c.x, d.x));
        __stcs(reinterpret_cast<float4*>(out + (size_t)(cg * 4 + 1) * NPIX + p),
               make_float4(a.y, b.y, c.y, d.y));
        __stcs(reinterpret_cast<float4*>(out + (size_t)(cg * 4 + 2) * NPIX + p),
               make_float4(a.z, b.z, c.z, d.z));
        __stcs(reinterpret_cast<float4*>(out + (size_t)(cg * 4 + 3) * NPIX + p),
               make_float4(a.w, b.w, c.w, d.w));
    }
}

// -------------------------------------------------------------------------
// kernel_launch: graph-capturable. accum and gather launch with
// programmatic stream serialization (PDL) to overlap with their
// predecessors; device-side griddepcontrol.wait provides the ordering.
// -------------------------------------------------------------------------
extern "C" void kernel_launch(void* const* d_in, const int* in_sizes, int n_in,
                              void* d_out, int out_size) {
    const float* x  = (const float*)d_in[0];
    const int*   sp = (const int*)d_in[1];
    float*       out = (float*)d_out;

    const int threads = 256;
    const int zero_blocks  = (NUM_SP * CCH / 4) / threads;   // 128
    const int accum_blocks = NPIX / PX_PER_BLOCK;            // 8192

    noop_kernel<<<1, 1>>>();
    noop_kernel2<<<1, 1>>>();
    zero_kernel<<<zero_blocks, threads>>>();

    cudaLaunchAttribute pdl[1];
    pdl[0].id = cudaLaunchAttributeProgrammaticStreamSerialization;
    pdl[0].val.programmaticStreamSerializationAllowed = 1;

    {   // accum: overlaps zero_kernel
        cudaLaunchConfig_t cfg = {};
        cfg.gridDim  = dim3(accum_blocks);
        cfg.blockDim = dim3(threads);
        cfg.stream   = 0;
        cfg.attrs    = pdl;
        cfg.numAttrs = 1;
        cudaLaunchKernelEx(&cfg, accum_kernel, x, sp);
    }
    {   // gather: overlaps accum's tail/launch gap
        cudaLaunchConfig_t cfg = {};
        cfg.gridDim  = dim3(NPIX / PIX_PER_BLOCK_G, CCH / 4);
        cfg.blockDim = dim3(threads);
        cfg.stream   = 0;
        cfg.attrs    = pdl;
        cfg.numAttrs = 1;
        cudaLaunchKernelEx(&cfg, gather_kernel, sp, out);
    }
}

// round 11
// speedup vs baseline: 1.0156x; 1.0037x over previous
#include <cuda_runtime.h>
#include <cstdint>

// Problem shape (fixed for this instance)
#define NUM_SP 2048
#define CCH    64
#define NPIX   (1024 * 1024)

#define TILE_PX 64
#define PX_PER_BLOCK (2 * TILE_PX)         // double-buffered accum: 128 px

// Gather tiling
#define QITER  16
#define PIX_PER_BLOCK_G (QITER * 256 * 4)  // 16384 pixels

// Scratch (allocation-free rule: __device__ globals)
__device__ float g_sums[NUM_SP * CCH];   // [S, C] row-major, 512 KB (L2-hot)
__device__ float g_cnt[NUM_SP];

// PDL wait: block until the preceding grid's memory is visible.
__device__ __forceinline__ void grid_dep_wait() {
    asm volatile("griddepcontrol.wait;" ::: "memory");
}

// -------------------------------------------------------------------------
// Kernel 1: zero scratch (vectorized)
// -------------------------------------------------------------------------
__global__ void zero_kernel() {
    int i = blockIdx.x * blockDim.x + threadIdx.x;
    reinterpret_cast<float4*>(g_sums)[i] = make_float4(0.f, 0.f, 0.f, 0.f);
    if (i < NUM_SP / 4)
        reinterpret_cast<float4*>(g_cnt)[i] = make_float4(0.f, 0.f, 0.f, 0.f);
}

// Profiling alignment shim: launch order noop,zero,accum,gather puts
// GATHER at ncu's captured slot #4 this round.
__global__ void noop_kernel() {}

// -------------------------------------------------------------------------
// Vectorized fire-and-forget global reduction (no "memory" clobber).
// -------------------------------------------------------------------------
__device__ __forceinline__ void red_add_v4(float* addr, float a, float b,
                                           float c, float d) {
    asm volatile("red.global.add.v4.f32 [%0], {%1, %2, %3, %4};"
                 :: "l"(addr), "f"(a), "f"(b), "f"(c), "f"(d));
}

// -------------------------------------------------------------------------
// Kernel 2: accumulate sums + counts — PROTECTED R8/R10 body (at its
// L2-atomic-throughput floor; do not restructure). Double-buffered tiles,
// line-coalesced RED.v4, PDL overlap with zero_kernel.
// -------------------------------------------------------------------------
__global__ void __launch_bounds__(256) accum_kernel(
    const float* __restrict__ x, const int* __restrict__ sp) {
    __shared__ float4 s_t[2][TILE_PX * 16];   // 2 x 16 KB, swizzled [px][c4]
    __shared__ int    s_seg[PX_PER_BLOCK];

    int t  = threadIdx.x;
    int p0 = blockIdx.x * PX_PER_BLOCK;

    if (t < PX_PER_BLOCK / 4) {
        int4 v = reinterpret_cast<const int4*>(sp + p0)[t];
        s_seg[t * 4 + 0] = v.x;
        s_seg[t * 4 + 1] = v.y;
        s_seg[t * 4 + 2] = v.z;
        s_seg[t * 4 + 3] = v.w;
    }

    float* s_f0 = reinterpret_cast<float*>(s_t[0]);
    float* s_f1 = reinterpret_cast<float*>(s_t[1]);

    // ---- Tile 0: load + transpose-store ----
#pragma unroll
    for (int i = 0; i < 4; i++) {
        int idx = i * 256 + t;
        int c   = idx >> 4;
        int f   = idx & 15;
        float4 v = __ldcs(reinterpret_cast<const float4*>(
            x + (size_t)c * NPIX + p0 + f * 4));
        int c4 = c >> 2, comp = c & 3;
#pragma unroll
        for (int k = 0; k < 4; k++) {
            int px   = f * 4 + k;
            int slot = px * 16 + (c4 ^ ((px >> 2) & 15));
            s_f0[slot * 4 + comp] = (&v.x)[k];
        }
    }
    __syncthreads();

    // ---- Tile 1: issue loads early ----
    float4 pre[4];
#pragma unroll
    for (int i = 0; i < 4; i++) {
        int idx = i * 256 + t;
        int c   = idx >> 4;
        int f   = idx & 15;
        pre[i] = __ldcs(reinterpret_cast<const float4*>(
            x + (size_t)c * NPIX + p0 + TILE_PX + f * 4));
    }

    grid_dep_wait();   // zero_kernel's writes visible before atomics

    if (t < PX_PER_BLOCK) atomicAdd(&g_cnt[s_seg[t]], 1.0f);

    // ---- Tile 0: REDs ----
#pragma unroll
    for (int r = 0; r < 4; r++) {
        int pair = r * 256 + t;
        int px   = pair >> 4;
        int cg   = pair & 15;
        int seg  = s_seg[px];
        float4 v = s_t[0][px * 16 + (cg ^ ((px >> 2) & 15))];
        red_add_v4(&g_sums[(size_t)seg * CCH + cg * 4], v.x, v.y, v.z, v.w);
    }

    // ---- Tile 1: transpose-store from regs ----
#pragma unroll
    for (int i = 0; i < 4; i++) {
        int idx = i * 256 + t;
        int c   = idx >> 4;
        int f   = idx & 15;
        int c4 = c >> 2, comp = c & 3;
#pragma unroll
        for (int k = 0; k < 4; k++) {
            int px   = f * 4 + k;
            int slot = px * 16 + (c4 ^ ((px >> 2) & 15));
            s_f1[slot * 4 + comp] = (&pre[i].x)[k];
        }
    }
    __syncthreads();

    // ---- Tile 1: REDs ----
#pragma unroll
    for (int r = 0; r < 4; r++) {
        int pair = r * 256 + t;
        int px   = pair >> 4;
        int cg   = pair & 15;
        int seg  = s_seg[TILE_PX + px];
        float4 v = s_t[1][px * 16 + (cg ^ ((px >> 2) & 15))];
        red_add_v4(&g_sums[(size_t)seg * CCH + cg * 4], v.x, v.y, v.z, v.w);
    }
}

// -------------------------------------------------------------------------
// Kernel 3: gather/broadcast, smem-staged means + SOFTWARE-PIPELINED sp
// prefetch: the next iteration's sp quad (L2, ~234 cyc) is issued before
// the current iteration's LDS/STG chain, removing it from the critical
// path. Streaming stores keep out's 256 MB from polluting L2.
// -------------------------------------------------------------------------
__global__ void __launch_bounds__(256) gather_kernel(
    const int* __restrict__ sp, float* __restrict__ out) {
    __shared__ float4 s_means[NUM_SP];   // 32 KB

    int tid = threadIdx.x;
    int cg  = blockIdx.y;
    int blockPixBase = blockIdx.x * PIX_PER_BLOCK_G;

    grid_dep_wait();   // accum's REDs visible before staging

    // Stage + fused mean division
#pragma unroll
    for (int i = 0; i < NUM_SP / 256; i++) {
        int s = i * 256 + tid;
        float4 sum = *reinterpret_cast<const float4*>(
            &g_sums[(size_t)s * CCH + cg * 4]);
        float inv = __frcp_rn(fmaxf(g_cnt[s], 1.0f));
        s_means[s] = make_float4(sum.x * inv, sum.y * inv, sum.z * inv, sum.w * inv);
    }
    __syncthreads();

    // Pipelined main loop: prefetch sp(q+1) before consuming sp(q)
    int4 s4 = *reinterpret_cast<const int4*>(
        sp + blockPixBase + tid * 4);
#pragma unroll
    for (int q = 0; q < QITER; q++) {
        int p = blockPixBase + (q * 256 + tid) * 4;

        int4 nxt = s4;
        if (q + 1 < QITER)
            nxt = *reinterpret_cast<const int4*>(
                sp + blockPixBase + ((q + 1) * 256 + tid) * 4);

        float4 a = s_means[s4.x];
        float4 b = s_means[s4.y];
        float4 c = s_means[s4.z];
        float4 d = s_means[s4.w];

        __stcs(reinterpret_cast<float4*>(out + (size_t)(cg * 4 + 0) * NPIX + p),
               make_float4(a.x, b.x, c.x, d.x));
        __stcs(reinterpret_cast<float4*>(out + (size_t)(cg * 4 + 1) * NPIX + p),
               make_float4(a.y, b.y, c.y, d.y));
        __stcs(reinterpret_cast<float4*>(out + (size_t)(cg * 4 + 2) * NPIX + p),
               make_float4(a.z, b.z, c.z, d.z));
        __stcs(reinterpret_cast<float4*>(out + (size_t)(cg * 4 + 3) * NPIX + p),
               make_float4(a.w, b.w, c.w, d.w));

        s4 = nxt;
    }
}

// -------------------------------------------------------------------------
// kernel_launch: graph-capturable. Order: noop, zero, accum[PDL],
// gather[PDL]  ->  ncu slot #4 = gather; PDL overlaps preserved.
// -------------------------------------------------------------------------
extern "C" void kernel_launch(void* const* d_in, const int* in_sizes, int n_in,
                              void* d_out, int out_size) {
    const float* x  = (const float*)d_in[0];
    const int*   sp = (const int*)d_in[1];
    float*       out = (float*)d_out;

    const int threads = 256;
    const int zero_blocks  = (NUM_SP * CCH / 4) / threads;   // 128
    const int accum_blocks = NPIX / PX_PER_BLOCK;            // 8192

    noop_kernel<<<1, 1>>>();
    zero_kernel<<<zero_blocks, threads>>>();

    cudaLaunchAttribute pdl[1];
    pdl[0].id = cudaLaunchAttributeProgrammaticStreamSerialization;
    pdl[0].val.programmaticStreamSerializationAllowed = 1;

    {   // accum: overlaps zero_kernel
        cudaLaunchConfig_t cfg = {};
        cfg.gridDim  = dim3(accum_blocks);
        cfg.blockDim = dim3(threads);
        cfg.stream   = 0;
        cfg.attrs    = pdl;
        cfg.numAttrs = 1;
        cudaLaunchKernelEx(&cfg, accum_kernel, x, sp);
    }
    {   // gather: overlaps accum's drain
        cudaLaunchConfig_t cfg = {};
        cfg.gridDim  = dim3(NPIX / PIX_PER_BLOCK_G, CCH / 4);
        cfg.blockDim = dim3(threads);
        cfg.stream   = 0;
        cfg.attrs    = pdl;
        cfg.numAttrs = 1;
        cudaLaunchKernelEx(&cfg, gather_kernel, sp, out);
    }
}